// round 4
// baseline (speedup 1.0000x reference)
#include <cuda_runtime.h>
#include <stdint.h>
#include <math.h>

#define BB 4
#define CC 256
#define LLEN 4096
#define NN 16
#define EPSF 1e-7f
#define OUT_MAIN (BB*CC*LLEN)

__device__ float g_fsa[BB*CC*LLEN];
__device__ float g_xr [BB*CC*LLEN];
__device__ float g_xo [BB*CC*LLEN];
__device__ float g_att[BB*NN*LLEN];
__device__ float g_R  [BB*CC*LLEN];
__device__ float g_S  [BB*CC*LLEN];
__device__ float g_fpos[BB*CC*NN];
__device__ float g_P[BB*CC*NN];
__device__ float g_Q[BB*CC*NN];
__device__ float g_cnt[BB*NN];
__device__ int   g_idx1[BB*32];
__device__ int   g_idx2[BB*32];

// ---------- Threefry-2x32-20 ----------
__device__ __forceinline__ uint32_t rotl32(uint32_t v,int r){return (v<<r)|(v>>(32-r));}
__device__ __forceinline__ void tf2x32(uint32_t k0,uint32_t k1,uint32_t x0,uint32_t x1,
                                       uint32_t&o0,uint32_t&o1){
  uint32_t ks2=k0^k1^0x1BD11BDAu;
  x0+=k0; x1+=k1;
#define TFR(r) { x0+=x1; x1=rotl32(x1,r); x1^=x0; }
  TFR(13)TFR(15)TFR(26)TFR(6)  x0+=k1;  x1+=ks2+1u;
  TFR(17)TFR(29)TFR(16)TFR(24) x0+=ks2; x1+=k0+2u;
  TFR(13)TFR(15)TFR(26)TFR(6)  x0+=k0;  x1+=k1+3u;
  TFR(17)TFR(29)TFR(16)TFR(24) x0+=k1;  x1+=ks2+4u;
  TFR(13)TFR(15)TFR(26)TFR(6)  x0+=ks2; x1+=k0+5u;
#undef TFR
  o0=x0; o1=x1;
}
// split(key(42),3): counts iota(6) -> pairs (i,i+3); out = concat(o0s,o1s) reshape(3,2)
__device__ __forceinline__ void jax_subkeys(uint32_t*r1,uint32_t*r2,uint32_t*r3){
  uint32_t a0,a1,b0,b1,c0,c1;
  tf2x32(0u,42u,0u,3u,a0,a1);
  tf2x32(0u,42u,1u,4u,b0,b1);
  tf2x32(0u,42u,2u,5u,c0,c1);
  r1[0]=a0; r1[1]=b0;  r2[0]=c0; r2[1]=a1;  r3[0]=b1; r3[1]=c1;
}
__device__ __forceinline__ float gumbel_bits(uint32_t bits){
  float f=__uint_as_float((bits>>9)|0x3f800000u)-1.0f;
  float u=fmaxf(1e-20f, f*(1.0f-1e-20f)+1e-20f);
  return -logf(-logf(u));
}

// ---------- tiled SGEMM: Y[b] = W[b] (CCxK) @ X[b] (KxLLEN) + bias ----------
#define BM 64
#define BN 64
#define BK 16
__global__ void __launch_bounds__(256) k_gemm(const float* __restrict__ W,
                                              const float* __restrict__ bias,
                                              const float* __restrict__ X,
                                              float* __restrict__ Y,
                                              int K,int wStrideB){
  __shared__ float As[BK][BM];
  __shared__ float Bs[BK][BN+4];
  int b=blockIdx.z;
  const float* Wb=W+(size_t)b*wStrideB;
  const float* Xb=X+(size_t)b*K*LLEN;
  float* Yb=Y+(size_t)b*CC*LLEN;
  int m0=blockIdx.y*BM, l0=blockIdx.x*BN, tid=threadIdx.x;
  int tx=tid&15, ty=tid>>4;
  int aRow=tid>>2, aCol=(tid&3)*4;
  int bRow=tid>>4, bCol=(tid&15)*4;
  float acc[4][4];
#pragma unroll
  for(int i=0;i<4;i++)
#pragma unroll
    for(int j=0;j<4;j++) acc[i][j]=0.f;
  for(int k0=0;k0<K;k0+=BK){
    float4 wv=*(const float4*)(Wb+(size_t)(m0+aRow)*K+k0+aCol);
    As[aCol][aRow]=wv.x; As[aCol+1][aRow]=wv.y; As[aCol+2][aRow]=wv.z; As[aCol+3][aRow]=wv.w;
    float4 xv=*(const float4*)(Xb+(size_t)(k0+bRow)*LLEN+l0+bCol);
    Bs[bRow][bCol]=xv.x; Bs[bRow][bCol+1]=xv.y; Bs[bRow][bCol+2]=xv.z; Bs[bRow][bCol+3]=xv.w;
    __syncthreads();
#pragma unroll
    for(int kk=0;kk<BK;kk++){
      float a0=As[kk][ty*4+0],a1=As[kk][ty*4+1],a2=As[kk][ty*4+2],a3=As[kk][ty*4+3];
      float b0=Bs[kk][tx*4+0],b1=Bs[kk][tx*4+1],b2=Bs[kk][tx*4+2],b3=Bs[kk][tx*4+3];
      acc[0][0]=fmaf(a0,b0,acc[0][0]); acc[0][1]=fmaf(a0,b1,acc[0][1]);
      acc[0][2]=fmaf(a0,b2,acc[0][2]); acc[0][3]=fmaf(a0,b3,acc[0][3]);
      acc[1][0]=fmaf(a1,b0,acc[1][0]); acc[1][1]=fmaf(a1,b1,acc[1][1]);
      acc[1][2]=fmaf(a1,b2,acc[1][2]); acc[1][3]=fmaf(a1,b3,acc[1][3]);
      acc[2][0]=fmaf(a2,b0,acc[2][0]); acc[2][1]=fmaf(a2,b1,acc[2][1]);
      acc[2][2]=fmaf(a2,b2,acc[2][2]); acc[2][3]=fmaf(a2,b3,acc[2][3]);
      acc[3][0]=fmaf(a3,b0,acc[3][0]); acc[3][1]=fmaf(a3,b1,acc[3][1]);
      acc[3][2]=fmaf(a3,b2,acc[3][2]); acc[3][3]=fmaf(a3,b3,acc[3][3]);
    }
    __syncthreads();
  }
#pragma unroll
  for(int i=0;i<4;i++){
    float bv=bias?bias[m0+ty*4+i]:0.0f;
    float* yr=Yb+(size_t)(m0+ty*4+i)*LLEN+l0+tx*4;
    yr[0]=acc[i][0]+bv; yr[1]=acc[i][1]+bv; yr[2]=acc[i][2]+bv; yr[3]=acc[i][3]+bv;
  }
}

// ---------- orth loss ----------
__global__ void k_orth(const float* __restrict__ kn, float* __restrict__ out_loss){
  __shared__ float sym[NN][NN];
  __shared__ float red[256];
  int tid=threadIdx.x, i=tid>>4, j=tid&15;
  float s=0.f;
  for(int c=0;c<CC;c++) s=fmaf(kn[i*CC+c],kn[j*CC+c],s);
  sym[i][j]=s; __syncthreads();
  float l=sym[i][j]/(sqrtf(sym[i][i])*sqrtf(sym[j][j])+EPSF)-((i==j)?1.0f:0.0f);
  red[tid]=l*l; __syncthreads();
  for(int sh=128;sh;sh>>=1){ if(tid<sh) red[tid]+=red[tid+sh]; __syncthreads(); }
  if(tid==0) *out_loss = 0.001f*logf(red[0]+1.0f);
}

// ---------- gumbel top-32 over mask / 1-mask ----------
__global__ void __launch_bounds__(256) k_sample(const float* __restrict__ mask){
  __shared__ float sc[LLEN];
  __shared__ float rv[256]; __shared__ int ri[256];
  int b=blockIdx.x, tid=threadIdx.x;
  uint32_t r1[2],r2[2],r3[2]; jax_subkeys(r1,r2,r3);
  for(int pass=0;pass<2;pass++){
    const uint32_t* key = pass?r2:r1;
    for(int l=tid;l<LLEN;l+=256){
      int j=b*LLEN+l;
      uint32_t i=(uint32_t)(j&8191), o0,o1;
      tf2x32(key[0],key[1],i,i+8192u,o0,o1);
      uint32_t bits=(j<8192)?o0:o1;
      float wv=mask[j]; if(pass) wv=1.0f-wv;
      sc[l]=logf(wv+1e-20f)+gumbel_bits(bits);
    }
    __syncthreads();
    int* outI = pass?(g_idx2+b*32):(g_idx1+b*32);
    for(int j=0;j<32;j++){
      float bv=-INFINITY; int bi=LLEN;
      for(int l=tid;l<LLEN;l+=256){
        float v=sc[l];
        if(v>bv||(v==bv&&l<bi)){bv=v;bi=l;}
      }
      rv[tid]=bv; ri[tid]=bi; __syncthreads();
      for(int s=128;s;s>>=1){
        if(tid<s){
          float v2=rv[tid+s]; int i2=ri[tid+s];
          if(v2>rv[tid]||(v2==rv[tid]&&i2<ri[tid])){rv[tid]=v2;ri[tid]=i2;}
        }
        __syncthreads();
      }
      if(tid==0){ outI[j]=ri[0]; sc[ri[0]]=-INFINITY; }
      __syncthreads();
    }
    __syncthreads();
  }
}

// ---------- relation -> factor2 -> final selection -> gather filters_pos ----------
__global__ void __launch_bounds__(256) k_select(){
  __shared__ float rel[32*32];
  __shared__ float nf[32],nx[32],f2[32];
  __shared__ int im[32],ik[32],selm[NN];
  int b=blockIdx.x, tid=threadIdx.x;
  if(tid<32){ im[tid]=g_idx1[b*32+tid]; ik[tid]=g_idx2[b*32+tid]; }
  __syncthreads();
  const float* Fb=g_fsa+(size_t)b*CC*LLEN;
  const float* Xb=g_xr +(size_t)b*CC*LLEN;
  if(tid<64){
    int m=tid&31;
    const float* base=(tid<32)?Fb:Xb;
    int pos=(tid<32)?im[m]:ik[m];
    float s=0.f;
    for(int c=0;c<CC;c++){ float v=base[(size_t)c*LLEN+pos]; s=fmaf(v,v,s); }
    if(tid<32) nf[m]=sqrtf(s); else nx[m]=sqrtf(s);
  }
  for(int p=tid;p<1024;p+=256){
    int m=p>>5,k=p&31, pm=im[m],pk=ik[k];
    float s=0.f;
#pragma unroll 4
    for(int c=0;c<CC;c++) s=fmaf(Fb[(size_t)c*LLEN+pm],Xb[(size_t)c*LLEN+pk],s);
    rel[p]=s;
  }
  __syncthreads();
  if(tid<32){
    float mx=-INFINITY;
    for(int k=0;k<32;k++) mx=fmaxf(mx, rel[tid*32+k]/(nf[tid]*nx[k]+EPSF));
    f2[tid]=mx;
  }
  __syncthreads();
  if(tid==0){
    float mx=-INFINITY;
    for(int m=0;m<32;m++) mx=fmaxf(mx,f2[m]);
    float s=0.f;
    for(int m=0;m<32;m++){ f2[m]=expf(f2[m]-mx); s+=f2[m]; }
    uint32_t r1k[2],r2k[2],r3k[2]; jax_subkeys(r1k,r2k,r3k);
    for(int m=0;m<32;m++){
      int j=b*32+m;
      uint32_t i=(uint32_t)(j&63),o0,o1;
      tf2x32(r3k[0],r3k[1],i,i+64u,o0,o1);
      uint32_t bits=(j<64)?o0:o1;
      f2[m]=logf(f2[m]/s+1e-20f)+gumbel_bits(bits);
    }
    for(int j=0;j<NN;j++){
      float bv=-INFINITY; int bi=0;
      for(int m=0;m<32;m++) if(f2[m]>bv){bv=f2[m];bi=m;}
      selm[j]=bi; f2[bi]=-INFINITY;
    }
  }
  __syncthreads();
  int c=tid;
  for(int j=0;j<NN;j++)
    g_fpos[((size_t)b*CC+c)*NN+j]=Fb[(size_t)c*LLEN+im[selm[j]]];
}

// ---------- fused act_pos + xn + softmax over n ----------
__global__ void __launch_bounds__(128) k_att(const float* __restrict__ x,
                                             const float* __restrict__ kn,
                                             const float* __restrict__ alpha){
  __shared__ float fp_s[CC*NN];
  __shared__ float kn_s[CC*NN];
  __shared__ float al_s[NN];
  int b=blockIdx.y, tid=threadIdx.x;
  int l=blockIdx.x*128+tid;
  for(int i=tid;i<CC*NN;i+=128){
    fp_s[i]=g_fpos[(size_t)b*CC*NN+i];
    int c=i>>4, n=i&15;
    kn_s[i]=kn[n*CC+c];
  }
  if(tid<NN) al_s[tid]=fminf(fmaxf(alpha[tid],0.0f),1.0f);
  __syncthreads();
  float aa[NN],ax[NN];
#pragma unroll
  for(int n=0;n<NN;n++){aa[n]=0.f;ax[n]=0.f;}
  const float* xrp=g_xr+(size_t)b*CC*LLEN+l;
  const float* xp =x   +(size_t)b*CC*LLEN+l;
  for(int c=0;c<CC;c++){
    float xrv=__ldg(xrp+(size_t)c*LLEN);
    float xv =__ldg(xp +(size_t)c*LLEN);
    const float* fr=fp_s+c*NN;
    const float* kr=kn_s+c*NN;
#pragma unroll
    for(int n=0;n<NN;n++){
      aa[n]=fmaf(xrv,fr[n],aa[n]);
      ax[n]=fmaf(xv ,kr[n],ax[n]);
    }
  }
  float lg[NN],mx=-INFINITY;
#pragma unroll
  for(int n=0;n<NN;n++){ lg[n]=(al_s[n]*aa[n]+ax[n])*0.1f; mx=fmaxf(mx,lg[n]); }
  float s=0.f;
#pragma unroll
  for(int n=0;n<NN;n++){ lg[n]=expf(lg[n]-mx); s+=lg[n]; }
  float inv=1.0f/s;
#pragma unroll
  for(int n=0;n<NN;n++) g_att[((size_t)b*NN+n)*LLEN+l]=lg[n]*inv;
}

// ---------- cnt ----------
__global__ void __launch_bounds__(256) k_cnt(){
  __shared__ float r[256];
  int n=blockIdx.x,b=blockIdx.y,tid=threadIdx.x;
  const float* a=g_att+((size_t)b*NN+n)*LLEN;
  float s=0.f;
  for(int l=tid;l<LLEN;l+=256) s+=a[l];
  r[tid]=s; __syncthreads();
  for(int sh=128;sh;sh>>=1){ if(tid<sh) r[tid]+=r[tid+sh]; __syncthreads(); }
  if(tid==0) g_cnt[b*NN+n]=r[0]+EPSF;
}

// ---------- per-(b,c,n) weighted moments -> P=1/(std+eps), Q=mean*P ----------
__global__ void __launch_bounds__(256) k_stats(){
  __shared__ float att_s[NN][258];
  __shared__ float xo_s[16][258];
  int b=blockIdx.y, c0=blockIdx.x*16, tid=threadIdx.x;
  int cr=tid>>4, n=tid&15;
  float s1=0.f,s2=0.f;
  for(int l0=0;l0<LLEN;l0+=256){
    for(int i=tid;i<16*256;i+=256){
      int r=i>>8, lc=i&255;
      att_s[r][lc]=g_att[((size_t)b*NN+r)*LLEN+l0+lc];
      xo_s [r][lc]=g_xo[((size_t)b*CC+c0+r)*LLEN+l0+lc];
    }
    __syncthreads();
#pragma unroll 4
    for(int lc=0;lc<256;lc+=2){
      float2 xv=*(float2*)&xo_s[cr][lc];
      float2 av=*(float2*)&att_s[n][lc];
      float h0=xv.x*av.x, h1=xv.y*av.y;
      s1+=h0+h1; s2=fmaf(h0,h0,fmaf(h1,h1,s2));
    }
    __syncthreads();
  }
  float cnt=g_cnt[b*NN+n];
  float mean=s1/cnt;
  float varsum=fmaf((float)LLEN*mean,mean, s2-2.0f*mean*s1);
  float stdv=sqrtf(fmaxf(varsum,0.0f)/cnt);
  float p=1.0f/(stdv+EPSF);
  size_t o=((size_t)b*CC+c0+cr)*NN+n;
  g_P[o]=p; g_Q[o]=mean*p;
}

// ---------- epilogue ----------
__global__ void __launch_bounds__(256) k_final(const float* __restrict__ x,
                                               const float* __restrict__ sigma,
                                               float* __restrict__ out){
  int idx=blockIdx.x*256+threadIdx.x;
  float sg=sigma[0];
  out[idx]=x[idx]+sg*(g_xo[idx]*g_R[idx]-g_S[idx]);
}

extern "C" void kernel_launch(void* const* d_in, const int* in_sizes, int n_in,
                              void* d_out, int out_size){
  const float* x    =(const float*)d_in[0];
  const float* f    =(const float*)d_in[1];
  const float* mask =(const float*)d_in[2];
  const float* ksa_w=(const float*)d_in[3];
  const float* ksa_b=(const float*)d_in[4];
  const float* kr_w =(const float*)d_in[5];
  const float* kr_b =(const float*)d_in[6];
  const float* kn   =(const float*)d_in[7];
  const float* ko_w =(const float*)d_in[8];
  const float* ko_b =(const float*)d_in[9];
  const float* alpha=(const float*)d_in[10];
  const float* sigma=(const float*)d_in[11];
  float* out=(float*)d_out;

  float *fsa,*xr,*xo,*att,*R,*S,*P,*Q;
  cudaGetSymbolAddress((void**)&fsa,g_fsa);
  cudaGetSymbolAddress((void**)&xr ,g_xr);
  cudaGetSymbolAddress((void**)&xo ,g_xo);
  cudaGetSymbolAddress((void**)&att,g_att);
  cudaGetSymbolAddress((void**)&R  ,g_R);
  cudaGetSymbolAddress((void**)&S  ,g_S);
  cudaGetSymbolAddress((void**)&P  ,g_P);
  cudaGetSymbolAddress((void**)&Q  ,g_Q);

  dim3 gg(LLEN/BN, CC/BM, BB);
  k_gemm<<<gg,256>>>(ksa_w,ksa_b,f,fsa,CC,0);
  k_gemm<<<gg,256>>>(kr_w ,kr_b ,x,xr ,CC,0);
  k_gemm<<<gg,256>>>(ko_w ,ko_b ,x,xo ,CC,0);
  k_orth<<<1,256>>>(kn, out+(out_size-1));
  k_sample<<<BB,256>>>(mask);
  k_select<<<BB,256>>>();
  k_att<<<dim3(LLEN/128,BB),128>>>(x,kn,alpha);
  k_cnt<<<dim3(NN,BB),256>>>();
  k_stats<<<dim3(CC/16,BB),256>>>();
  k_gemm<<<gg,256>>>(P,nullptr,att,R,NN,CC*NN);
  k_gemm<<<gg,256>>>(Q,nullptr,att,S,NN,CC*NN);
  k_final<<<OUT_MAIN/256,256>>>(x,sigma,out);
}

// round 5
// speedup vs baseline: 1.2160x; 1.2160x over previous
#include <cuda_runtime.h>
#include <stdint.h>
#include <math.h>

#define BB 4
#define CC 256
#define LLEN 4096
#define NN 16
#define EPSF 1e-7f
#define OUT_MAIN (BB*CC*LLEN)

__device__ float g_fsa[BB*CC*LLEN];
__device__ float g_xr [BB*CC*LLEN];
__device__ float g_xo [BB*CC*LLEN];
__device__ float g_att[BB*NN*LLEN];
__device__ float g_fpos[BB*CC*NN];
__device__ float g_P[BB*CC*NN];
__device__ float g_Q[BB*CC*NN];
__device__ float g_cnt[BB*NN];
__device__ int   g_idx1[BB*32];
__device__ int   g_idx2[BB*32];

// ---------- Threefry-2x32-20 ----------
__device__ __forceinline__ uint32_t rotl32(uint32_t v,int r){return (v<<r)|(v>>(32-r));}
__device__ __forceinline__ void tf2x32(uint32_t k0,uint32_t k1,uint32_t x0,uint32_t x1,
                                       uint32_t&o0,uint32_t&o1){
  uint32_t ks2=k0^k1^0x1BD11BDAu;
  x0+=k0; x1+=k1;
#define TFR(r) { x0+=x1; x1=rotl32(x1,r); x1^=x0; }
  TFR(13)TFR(15)TFR(26)TFR(6)  x0+=k1;  x1+=ks2+1u;
  TFR(17)TFR(29)TFR(16)TFR(24) x0+=ks2; x1+=k0+2u;
  TFR(13)TFR(15)TFR(26)TFR(6)  x0+=k0;  x1+=k1+3u;
  TFR(17)TFR(29)TFR(16)TFR(24) x0+=k1;  x1+=ks2+4u;
  TFR(13)TFR(15)TFR(26)TFR(6)  x0+=ks2; x1+=k0+5u;
#undef TFR
  o0=x0; o1=x1;
}
__device__ __forceinline__ void jax_subkeys(uint32_t*r1,uint32_t*r2,uint32_t*r3){
  uint32_t a0,a1,b0,b1,c0,c1;
  tf2x32(0u,42u,0u,3u,a0,a1);
  tf2x32(0u,42u,1u,4u,b0,b1);
  tf2x32(0u,42u,2u,5u,c0,c1);
  r1[0]=a0; r1[1]=b0;  r2[0]=c0; r2[1]=a1;  r3[0]=b1; r3[1]=c1;
}
__device__ __forceinline__ float gumbel_bits(uint32_t bits){
  float f=__uint_as_float((bits>>9)|0x3f800000u)-1.0f;
  float u=fmaxf(1e-20f, f*(1.0f-1e-20f)+1e-20f);
  return -__logf(-__logf(u));
}

// ---------- tf32 tensor-core GEMM: Y[b] = W (256x256) @ X[b] (256xLLEN) + bias ----------
// block tile 128x64, BK=16, 256 threads (8 warps: 4 m x 2 n, warp tile 32x32)
#define GM 128
#define GN 64
#define GK 16
__device__ __forceinline__ void mma_tf32(float* c, const uint32_t* a, const uint32_t* b){
  asm volatile(
    "mma.sync.aligned.m16n8k8.row.col.f32.tf32.tf32.f32 "
    "{%0,%1,%2,%3}, {%4,%5,%6,%7}, {%8,%9}, {%0,%1,%2,%3};"
    : "+f"(c[0]),"+f"(c[1]),"+f"(c[2]),"+f"(c[3])
    : "r"(a[0]),"r"(a[1]),"r"(a[2]),"r"(a[3]), "r"(b[0]),"r"(b[1]));
}
__global__ void __launch_bounds__(256) k_gemm_tc(const float* __restrict__ W,
                                                 const float* __restrict__ bias,
                                                 const float* __restrict__ X,
                                                 float* __restrict__ Y){
  __shared__ float As[2][GM][20];   // [m][k], stride 20 -> conflict-free frag loads
  __shared__ float Bs[2][GK][72];   // [k][n], stride 72 -> conflict-free frag loads
  int b=blockIdx.z;
  const float* Xb=X+(size_t)b*CC*LLEN;
  float* Yb=Y+(size_t)b*CC*LLEN;
  int m0=blockIdx.y*GM, l0=blockIdx.x*GN, tid=threadIdx.x;
  int wid=tid>>5, lane=tid&31;
  int wm=(wid&3)*32, wn=(wid>>2)*32;
  int gid=lane>>2, tig=lane&3;

  int aRow=tid>>2, aKc=(tid&3)<<2;        // A: 2 float4 per thread (rows aRow, aRow+64)
  int bKr=tid>>4, bNc=(tid&15)<<2;        // B: 1 float4 per thread

  float acc[2][4][4];
#pragma unroll
  for(int i=0;i<2;i++)
#pragma unroll
    for(int j=0;j<4;j++)
#pragma unroll
      for(int k=0;k<4;k++) acc[i][j][k]=0.f;

  // preload tile 0
  {
    float4 pa0=*(const float4*)(W+(size_t)(m0+aRow)*CC+aKc);
    float4 pa1=*(const float4*)(W+(size_t)(m0+aRow+64)*CC+aKc);
    float4 pb =*(const float4*)(Xb+(size_t)bKr*LLEN+l0+bNc);
    *(float4*)&As[0][aRow][aKc]=pa0;
    *(float4*)&As[0][aRow+64][aKc]=pa1;
    *(float4*)&Bs[0][bKr][bNc]=pb;
  }
  __syncthreads();

  float4 pa0,pa1,pb;
  for(int kt=0;kt<CC/GK;kt++){
    int cur=kt&1;
    if(kt<CC/GK-1){
      int k0=(kt+1)*GK;
      pa0=*(const float4*)(W+(size_t)(m0+aRow)*CC+k0+aKc);
      pa1=*(const float4*)(W+(size_t)(m0+aRow+64)*CC+k0+aKc);
      pb =*(const float4*)(Xb+(size_t)(k0+bKr)*LLEN+l0+bNc);
    }
#pragma unroll
    for(int ks=0;ks<GK;ks+=8){
      uint32_t af[2][4], bf[4][2];
#pragma unroll
      for(int mt=0;mt<2;mt++){
        int m=wm+mt*16+gid;
        af[mt][0]=__float_as_uint(As[cur][m  ][ks+tig  ]);
        af[mt][1]=__float_as_uint(As[cur][m+8][ks+tig  ]);
        af[mt][2]=__float_as_uint(As[cur][m  ][ks+tig+4]);
        af[mt][3]=__float_as_uint(As[cur][m+8][ks+tig+4]);
      }
#pragma unroll
      for(int nt=0;nt<4;nt++){
        int n=wn+nt*8+gid;
        bf[nt][0]=__float_as_uint(Bs[cur][ks+tig  ][n]);
        bf[nt][1]=__float_as_uint(Bs[cur][ks+tig+4][n]);
      }
#pragma unroll
      for(int mt=0;mt<2;mt++)
#pragma unroll
        for(int nt=0;nt<4;nt++)
          mma_tf32(acc[mt][nt], af[mt], bf[nt]);
    }
    if(kt<CC/GK-1){
      int nxt=cur^1;
      *(float4*)&As[nxt][aRow][aKc]=pa0;
      *(float4*)&As[nxt][aRow+64][aKc]=pa1;
      *(float4*)&Bs[nxt][bKr][bNc]=pb;
    }
    __syncthreads();
  }

  // epilogue
#pragma unroll
  for(int mt=0;mt<2;mt++){
    int row=m0+wm+mt*16+gid;
    float bv0=bias[row], bv8=bias[row+8];
#pragma unroll
    for(int nt=0;nt<4;nt++){
      int col=l0+wn+nt*8+2*tig;
      float2 v0={acc[mt][nt][0]+bv0, acc[mt][nt][1]+bv0};
      float2 v8={acc[mt][nt][2]+bv8, acc[mt][nt][3]+bv8};
      *(float2*)(Yb+(size_t)row*LLEN+col)=v0;
      *(float2*)(Yb+(size_t)(row+8)*LLEN+col)=v8;
    }
  }
}

// ---------- orth loss ----------
__global__ void k_orth(const float* __restrict__ kn, float* __restrict__ out_loss){
  __shared__ float sym[NN][NN];
  __shared__ float red[256];
  int tid=threadIdx.x, i=tid>>4, j=tid&15;
  float s=0.f;
  for(int c=0;c<CC;c++) s=fmaf(kn[i*CC+c],kn[j*CC+c],s);
  sym[i][j]=s; __syncthreads();
  float l=sym[i][j]/(sqrtf(sym[i][i])*sqrtf(sym[j][j])+EPSF)-((i==j)?1.0f:0.0f);
  red[tid]=l*l; __syncthreads();
  for(int sh=128;sh;sh>>=1){ if(tid<sh) red[tid]+=red[tid+sh]; __syncthreads(); }
  if(tid==0) *out_loss = 0.001f*logf(red[0]+1.0f);
}

// ---------- gumbel top-32 over mask / 1-mask ----------
__global__ void __launch_bounds__(256) k_sample(const float* __restrict__ mask){
  __shared__ float sc[LLEN];
  __shared__ float rv[256]; __shared__ int ri[256];
  int b=blockIdx.x, tid=threadIdx.x;
  uint32_t r1[2],r2[2],r3[2]; jax_subkeys(r1,r2,r3);
  for(int pass=0;pass<2;pass++){
    const uint32_t* key = pass?r2:r1;
    for(int l=tid;l<LLEN;l+=256){
      int j=b*LLEN+l;
      uint32_t i=(uint32_t)(j&8191), o0,o1;
      tf2x32(key[0],key[1],i,i+8192u,o0,o1);
      uint32_t bits=(j<8192)?o0:o1;
      float wv=mask[j]; if(pass) wv=1.0f-wv;
      sc[l]=__logf(wv+1e-20f)+gumbel_bits(bits);
    }
    __syncthreads();
    int* outI = pass?(g_idx2+b*32):(g_idx1+b*32);
    for(int j=0;j<32;j++){
      float bv=-INFINITY; int bi=LLEN;
      for(int l=tid;l<LLEN;l+=256){
        float v=sc[l];
        if(v>bv||(v==bv&&l<bi)){bv=v;bi=l;}
      }
      rv[tid]=bv; ri[tid]=bi; __syncthreads();
      for(int s=128;s;s>>=1){
        if(tid<s){
          float v2=rv[tid+s]; int i2=ri[tid+s];
          if(v2>rv[tid]||(v2==rv[tid]&&i2<ri[tid])){rv[tid]=v2;ri[tid]=i2;}
        }
        __syncthreads();
      }
      if(tid==0){ outI[j]=ri[0]; sc[ri[0]]=-INFINITY; }
      __syncthreads();
    }
    __syncthreads();
  }
}

// ---------- relation -> factor2 -> final selection -> gather filters_pos ----------
__global__ void __launch_bounds__(256) k_select(){
  __shared__ float rel[32*32];
  __shared__ float nf[32],nx[32],f2[32];
  __shared__ int im[32],ik[32],selm[NN];
  int b=blockIdx.x, tid=threadIdx.x;
  if(tid<32){ im[tid]=g_idx1[b*32+tid]; ik[tid]=g_idx2[b*32+tid]; }
  __syncthreads();
  const float* Fb=g_fsa+(size_t)b*CC*LLEN;
  const float* Xb=g_xr +(size_t)b*CC*LLEN;
  if(tid<64){
    int m=tid&31;
    const float* base=(tid<32)?Fb:Xb;
    int pos=(tid<32)?im[m]:ik[m];
    float s=0.f;
    for(int c=0;c<CC;c++){ float v=base[(size_t)c*LLEN+pos]; s=fmaf(v,v,s); }
    if(tid<32) nf[m]=sqrtf(s); else nx[m]=sqrtf(s);
  }
  for(int p=tid;p<1024;p+=256){
    int m=p>>5,k=p&31, pm=im[m],pk=ik[k];
    float s=0.f;
#pragma unroll 4
    for(int c=0;c<CC;c++) s=fmaf(Fb[(size_t)c*LLEN+pm],Xb[(size_t)c*LLEN+pk],s);
    rel[p]=s;
  }
  __syncthreads();
  if(tid<32){
    float mx=-INFINITY;
    for(int k=0;k<32;k++) mx=fmaxf(mx, rel[tid*32+k]/(nf[tid]*nx[k]+EPSF));
    f2[tid]=mx;
  }
  __syncthreads();
  if(tid==0){
    float mx=-INFINITY;
    for(int m=0;m<32;m++) mx=fmaxf(mx,f2[m]);
    float s=0.f;
    for(int m=0;m<32;m++){ f2[m]=__expf(f2[m]-mx); s+=f2[m]; }
    uint32_t r1k[2],r2k[2],r3k[2]; jax_subkeys(r1k,r2k,r3k);
    for(int m=0;m<32;m++){
      int j=b*32+m;
      uint32_t i=(uint32_t)(j&63),o0,o1;
      tf2x32(r3k[0],r3k[1],i,i+64u,o0,o1);
      uint32_t bits=(j<64)?o0:o1;
      f2[m]=__logf(f2[m]/s+1e-20f)+gumbel_bits(bits);
    }
    for(int j=0;j<NN;j++){
      float bv=-INFINITY; int bi=0;
      for(int m=0;m<32;m++) if(f2[m]>bv){bv=f2[m];bi=m;}
      selm[j]=bi; f2[bi]=-INFINITY;
    }
  }
  __syncthreads();
  int c=tid;
  for(int j=0;j<NN;j++)
    g_fpos[((size_t)b*CC+c)*NN+j]=Fb[(size_t)c*LLEN+im[selm[j]]];
}

// ---------- fused act_pos + xn + softmax over n ----------
__global__ void __launch_bounds__(128) k_att(const float* __restrict__ x,
                                             const float* __restrict__ kn,
                                             const float* __restrict__ alpha){
  __shared__ float fp_s[CC*NN];
  __shared__ float kn_s[CC*NN];
  __shared__ float al_s[NN];
  int b=blockIdx.y, tid=threadIdx.x;
  int l=blockIdx.x*128+tid;
  for(int i=tid;i<CC*NN;i+=128){
    fp_s[i]=g_fpos[(size_t)b*CC*NN+i];
    int c=i>>4, n=i&15;
    kn_s[i]=kn[n*CC+c];
  }
  if(tid<NN) al_s[tid]=fminf(fmaxf(alpha[tid],0.0f),1.0f);
  __syncthreads();
  float aa[NN],ax[NN];
#pragma unroll
  for(int n=0;n<NN;n++){aa[n]=0.f;ax[n]=0.f;}
  const float* xrp=g_xr+(size_t)b*CC*LLEN+l;
  const float* xp =x   +(size_t)b*CC*LLEN+l;
  for(int c=0;c<CC;c++){
    float xrv=__ldg(xrp+(size_t)c*LLEN);
    float xv =__ldg(xp +(size_t)c*LLEN);
    const float* fr=fp_s+c*NN;
    const float* kr=kn_s+c*NN;
#pragma unroll
    for(int n=0;n<NN;n++){
      aa[n]=fmaf(xrv,fr[n],aa[n]);
      ax[n]=fmaf(xv ,kr[n],ax[n]);
    }
  }
  float lg[NN],mx=-INFINITY;
#pragma unroll
  for(int n=0;n<NN;n++){ lg[n]=(al_s[n]*aa[n]+ax[n])*0.1f; mx=fmaxf(mx,lg[n]); }
  float s=0.f;
#pragma unroll
  for(int n=0;n<NN;n++){ lg[n]=__expf(lg[n]-mx); s+=lg[n]; }
  float inv=1.0f/s;
#pragma unroll
  for(int n=0;n<NN;n++) g_att[((size_t)b*NN+n)*LLEN+l]=lg[n]*inv;
}

// ---------- cnt ----------
__global__ void __launch_bounds__(256) k_cnt(){
  __shared__ float r[256];
  int n=blockIdx.x,b=blockIdx.y,tid=threadIdx.x;
  const float* a=g_att+((size_t)b*NN+n)*LLEN;
  float s=0.f;
  for(int l=tid;l<LLEN;l+=256) s+=a[l];
  r[tid]=s; __syncthreads();
  for(int sh=128;sh;sh>>=1){ if(tid<sh) r[tid]+=r[tid+sh]; __syncthreads(); }
  if(tid==0) g_cnt[b*NN+n]=r[0]+EPSF;
}

// ---------- per-(b,c,n) weighted moments -> P=1/(std+eps), Q=mean*P ----------
__global__ void __launch_bounds__(256) k_stats(){
  __shared__ float att_s[NN][258];
  __shared__ float xo_s[16][258];
  int b=blockIdx.y, c0=blockIdx.x*16, tid=threadIdx.x;
  int cr=tid>>4, n=tid&15;
  float s1=0.f,s2=0.f;
  for(int l0=0;l0<LLEN;l0+=256){
    for(int i=tid;i<16*256;i+=256){
      int r=i>>8, lc=i&255;
      att_s[r][lc]=g_att[((size_t)b*NN+r)*LLEN+l0+lc];
      xo_s [r][lc]=g_xo[((size_t)b*CC+c0+r)*LLEN+l0+lc];
    }
    __syncthreads();
#pragma unroll 4
    for(int lc=0;lc<256;lc+=2){
      float2 xv=*(float2*)&xo_s[cr][lc];
      float2 av=*(float2*)&att_s[n][lc];
      float h0=xv.x*av.x, h1=xv.y*av.y;
      s1+=h0+h1; s2=fmaf(h0,h0,fmaf(h1,h1,s2));
    }
    __syncthreads();
  }
  float cnt=g_cnt[b*NN+n];
  float mean=s1/cnt;
  float varsum=fmaf((float)LLEN*mean,mean, s2-2.0f*mean*s1);
  float stdv=sqrtf(fmaxf(varsum,0.0f)/cnt);
  float p=1.0f/(stdv+EPSF);
  size_t o=((size_t)b*CC+c0+cr)*NN+n;
  g_P[o]=p; g_Q[o]=mean*p;
}

// ---------- fused K=16 GEMMs + epilogue: out = x + sg*(xo*(P.att) - (Q.att)) ----------
__global__ void __launch_bounds__(256) k_fuse(const float* __restrict__ x,
                                              const float* __restrict__ sigma,
                                              float* __restrict__ out){
  __shared__ float att_s[NN][64];
  __shared__ float P_s[16][16], Q_s[16][16];
  int b=blockIdx.z, c0=blockIdx.y*16, l0=blockIdx.x*64;
  int tid=threadIdx.x;
  for(int i=tid;i<NN*64;i+=256){
    int n=i>>6, l=i&63;
    att_s[n][l]=g_att[((size_t)b*NN+n)*LLEN+l0+l];
  }
  {
    int cl=tid>>4, n=tid&15;
    P_s[cl][n]=g_P[((size_t)b*CC+c0+cl)*NN+n];
    Q_s[cl][n]=g_Q[((size_t)b*CC+c0+cl)*NN+n];
  }
  __syncthreads();
  float sg=sigma[0];
  int ll=tid&63, cbase=tid>>6;
  for(int cc=cbase;cc<16;cc+=4){
    float r=0.f,s=0.f;
#pragma unroll
    for(int n=0;n<NN;n++){
      float a=att_s[n][ll];
      r=fmaf(P_s[cc][n],a,r);
      s=fmaf(Q_s[cc][n],a,s);
    }
    size_t o=((size_t)b*CC+c0+cc)*LLEN+l0+ll;
    out[o]=x[o]+sg*(g_xo[o]*r-s);
  }
}

extern "C" void kernel_launch(void* const* d_in, const int* in_sizes, int n_in,
                              void* d_out, int out_size){
  const float* x    =(const float*)d_in[0];
  const float* f    =(const float*)d_in[1];
  const float* mask =(const float*)d_in[2];
  const float* ksa_w=(const float*)d_in[3];
  const float* ksa_b=(const float*)d_in[4];
  const float* kr_w =(const float*)d_in[5];
  const float* kr_b =(const float*)d_in[6];
  const float* kn   =(const float*)d_in[7];
  const float* ko_w =(const float*)d_in[8];
  const float* ko_b =(const float*)d_in[9];
  const float* alpha=(const float*)d_in[10];
  const float* sigma=(const float*)d_in[11];
  float* out=(float*)d_out;

  float *fsa,*xr,*xo;
  cudaGetSymbolAddress((void**)&fsa,g_fsa);
  cudaGetSymbolAddress((void**)&xr ,g_xr);
  cudaGetSymbolAddress((void**)&xo ,g_xo);

  dim3 gg(LLEN/GN, CC/GM, BB);
  k_gemm_tc<<<gg,256>>>(ksa_w,ksa_b,f,fsa);
  k_gemm_tc<<<gg,256>>>(kr_w ,kr_b ,x,xr );
  k_gemm_tc<<<gg,256>>>(ko_w ,ko_b ,x,xo );
  k_orth<<<1,256>>>(kn, out+(out_size-1));
  k_sample<<<BB,256>>>(mask);
  k_select<<<BB,256>>>();
  k_att<<<dim3(LLEN/128,BB),128>>>(x,kn,alpha);
  k_cnt<<<dim3(NN,BB),256>>>();
  k_stats<<<dim3(CC/16,BB),256>>>();
  k_fuse<<<dim3(LLEN/64,CC/16,BB),256>>>(x,sigma,out);
}

// round 6
// speedup vs baseline: 1.6047x; 1.3196x over previous
#include <cuda_runtime.h>
#include <stdint.h>
#include <math.h>

#define BB 4
#define CC 256
#define LLEN 4096
#define NN 16
#define EPSF 1e-7f
#define OUT_MAIN (BB*CC*LLEN)

__device__ float g_xr [BB*CC*LLEN];
__device__ float g_xo [BB*CC*LLEN];
__device__ float g_att[BB*NN*LLEN];
__device__ float g_fpos[BB*CC*NN];
__device__ float g_P[BB*CC*NN];
__device__ float g_Q[BB*CC*NN];
__device__ float g_cnt[BB*NN];
__device__ int   g_idx1[BB*32];
__device__ int   g_idx2[BB*32];

// ---------- Threefry-2x32-20 ----------
__device__ __forceinline__ uint32_t rotl32(uint32_t v,int r){return (v<<r)|(v>>(32-r));}
__device__ __forceinline__ void tf2x32(uint32_t k0,uint32_t k1,uint32_t x0,uint32_t x1,
                                       uint32_t&o0,uint32_t&o1){
  uint32_t ks2=k0^k1^0x1BD11BDAu;
  x0+=k0; x1+=k1;
#define TFR(r) { x0+=x1; x1=rotl32(x1,r); x1^=x0; }
  TFR(13)TFR(15)TFR(26)TFR(6)  x0+=k1;  x1+=ks2+1u;
  TFR(17)TFR(29)TFR(16)TFR(24) x0+=ks2; x1+=k0+2u;
  TFR(13)TFR(15)TFR(26)TFR(6)  x0+=k0;  x1+=k1+3u;
  TFR(17)TFR(29)TFR(16)TFR(24) x0+=k1;  x1+=ks2+4u;
  TFR(13)TFR(15)TFR(26)TFR(6)  x0+=ks2; x1+=k0+5u;
#undef TFR
  o0=x0; o1=x1;
}
__device__ __forceinline__ void jax_subkeys(uint32_t*r1,uint32_t*r2,uint32_t*r3){
  uint32_t a0,a1,b0,b1,c0,c1;
  tf2x32(0u,42u,0u,3u,a0,a1);
  tf2x32(0u,42u,1u,4u,b0,b1);
  tf2x32(0u,42u,2u,5u,c0,c1);
  r1[0]=a0; r1[1]=b0;  r2[0]=c0; r2[1]=a1;  r3[0]=b1; r3[1]=c1;
}
__device__ __forceinline__ float gumbel_bits(uint32_t bits){
  float f=__uint_as_float((bits>>9)|0x3f800000u)-1.0f;
  float u=fmaxf(1e-20f, f*(1.0f-1e-20f)+1e-20f);
  return -__logf(-__logf(u));
}

// ---------- tf32 dual GEMM: Y0=W0@X+b0, Y1=W1@X+b1 (shared X tiles) ----------
#define GM 128
#define GN 64
#define GK 16
__device__ __forceinline__ void mma_tf32(float* c, const uint32_t* a, const uint32_t* b){
  asm volatile(
    "mma.sync.aligned.m16n8k8.row.col.f32.tf32.tf32.f32 "
    "{%0,%1,%2,%3}, {%4,%5,%6,%7}, {%8,%9}, {%0,%1,%2,%3};"
    : "+f"(c[0]),"+f"(c[1]),"+f"(c[2]),"+f"(c[3])
    : "r"(a[0]),"r"(a[1]),"r"(a[2]),"r"(a[3]), "r"(b[0]),"r"(b[1]));
}
// dsm layout: A: [(buf*2+w)*128+m]*20+k   (10240 floats)
//             B: 10240 + (buf*16+k)*72+n  (2304 floats)  total 50176 B
#define ASI(buf,w,m,k) dsm[(((buf)*2+(w))*GM+(m))*20+(k)]
#define BSI(buf,k,n)   dsm[10240+((buf)*GK+(k))*72+(n)]
__global__ void __launch_bounds__(256) k_gemm_dual(
    const float* __restrict__ W0,const float* __restrict__ b0,
    const float* __restrict__ W1,const float* __restrict__ b1,
    const float* __restrict__ X, float* __restrict__ Y0, float* __restrict__ Y1){
  extern __shared__ float dsm[];
  int b=blockIdx.z;
  const float* Xb=X+(size_t)b*CC*LLEN;
  int m0=blockIdx.y*GM, l0=blockIdx.x*GN, tid=threadIdx.x;
  int wid=tid>>5, lane=tid&31;
  int wm=(wid&3)*32, wn=(wid>>2)*32;
  int gid=lane>>2, tig=lane&3;
  int aRow=tid>>2, aKc=(tid&3)<<2;
  int bKr=tid>>4, bNc=(tid&15)<<2;
  const float* w0a=W0+(size_t)(m0+aRow)*CC+aKc;
  const float* w0b=W0+(size_t)(m0+aRow+64)*CC+aKc;
  const float* w1a=W1+(size_t)(m0+aRow)*CC+aKc;
  const float* w1b=W1+(size_t)(m0+aRow+64)*CC+aKc;
  float acc[2][2][4][4];
#pragma unroll
  for(int w=0;w<2;w++)
#pragma unroll
    for(int i=0;i<2;i++)
#pragma unroll
      for(int j=0;j<4;j++)
#pragma unroll
        for(int k=0;k<4;k++) acc[w][i][j][k]=0.f;

  *(float4*)&ASI(0,0,aRow,aKc)   =*(const float4*)(w0a);
  *(float4*)&ASI(0,0,aRow+64,aKc)=*(const float4*)(w0b);
  *(float4*)&ASI(0,1,aRow,aKc)   =*(const float4*)(w1a);
  *(float4*)&ASI(0,1,aRow+64,aKc)=*(const float4*)(w1b);
  *(float4*)&BSI(0,bKr,bNc)      =*(const float4*)(Xb+(size_t)bKr*LLEN+l0+bNc);
  __syncthreads();

  float4 p00,p01,p10,p11,pb;
  for(int kt=0;kt<CC/GK;kt++){
    int cur=kt&1;
    if(kt<CC/GK-1){
      int k0=(kt+1)*GK;
      p00=*(const float4*)(w0a+k0); p01=*(const float4*)(w0b+k0);
      p10=*(const float4*)(w1a+k0); p11=*(const float4*)(w1b+k0);
      pb =*(const float4*)(Xb+(size_t)(k0+bKr)*LLEN+l0+bNc);
    }
#pragma unroll
    for(int ks=0;ks<GK;ks+=8){
      uint32_t af[2][2][4], bf[4][2];
#pragma unroll
      for(int w=0;w<2;w++)
#pragma unroll
        for(int mt=0;mt<2;mt++){
          int m=wm+mt*16+gid;
          af[w][mt][0]=__float_as_uint(ASI(cur,w,m  ,ks+tig  ));
          af[w][mt][1]=__float_as_uint(ASI(cur,w,m+8,ks+tig  ));
          af[w][mt][2]=__float_as_uint(ASI(cur,w,m  ,ks+tig+4));
          af[w][mt][3]=__float_as_uint(ASI(cur,w,m+8,ks+tig+4));
        }
#pragma unroll
      for(int nt=0;nt<4;nt++){
        int n=wn+nt*8+gid;
        bf[nt][0]=__float_as_uint(BSI(cur,ks+tig  ,n));
        bf[nt][1]=__float_as_uint(BSI(cur,ks+tig+4,n));
      }
#pragma unroll
      for(int w=0;w<2;w++)
#pragma unroll
        for(int mt=0;mt<2;mt++)
#pragma unroll
          for(int nt=0;nt<4;nt++)
            mma_tf32(acc[w][mt][nt], af[w][mt], bf[nt]);
    }
    if(kt<CC/GK-1){
      int nxt=cur^1;
      *(float4*)&ASI(nxt,0,aRow,aKc)   =p00;
      *(float4*)&ASI(nxt,0,aRow+64,aKc)=p01;
      *(float4*)&ASI(nxt,1,aRow,aKc)   =p10;
      *(float4*)&ASI(nxt,1,aRow+64,aKc)=p11;
      *(float4*)&BSI(nxt,bKr,bNc)      =pb;
    }
    __syncthreads();
  }
#pragma unroll
  for(int w=0;w<2;w++){
    const float* bias = w ? b1 : b0;
    float* Yb = (w ? Y1 : Y0) + (size_t)b*CC*LLEN;
#pragma unroll
    for(int mt=0;mt<2;mt++){
      int row=m0+wm+mt*16+gid;
      float bv0=bias[row], bv8=bias[row+8];
#pragma unroll
      for(int nt=0;nt<4;nt++){
        int col=l0+wn+nt*8+2*tig;
        float2 v0={acc[w][mt][nt][0]+bv0, acc[w][mt][nt][1]+bv0};
        float2 v8={acc[w][mt][nt][2]+bv8, acc[w][mt][nt][3]+bv8};
        *(float2*)(Yb+(size_t)row*LLEN+col)=v0;
        *(float2*)(Yb+(size_t)(row+8)*LLEN+col)=v8;
      }
    }
  }
}

// ---------- orth loss (smem) ----------
__global__ void __launch_bounds__(256) k_orth(const float* __restrict__ kn,
                                              float* __restrict__ out_loss){
  __shared__ float ks[NN][260];
  __shared__ float sym[NN][17];
  __shared__ float red[256];
  int tid=threadIdx.x;
  for(int i=tid;i<NN*CC;i+=256) ks[i>>8][i&255]=kn[i];
  __syncthreads();
  int i=tid>>4, j=tid&15;
  float s=0.f;
#pragma unroll 8
  for(int c=0;c<CC;c++) s=fmaf(ks[i][c],ks[j][c],s);
  sym[i][j]=s; __syncthreads();
  float l=sym[i][j]/(sqrtf(sym[i][i])*sqrtf(sym[j][j])+EPSF)-((i==j)?1.0f:0.0f);
  red[tid]=l*l; __syncthreads();
  for(int sh=128;sh;sh>>=1){ if(tid<sh) red[tid]+=red[tid+sh]; __syncthreads(); }
  if(tid==0) *out_loss = 0.001f*logf(red[0]+1.0f);
}

// ---------- gumbel top-32 (u64-key shuffle argmax) ----------
__global__ void __launch_bounds__(256) k_sample(const float* __restrict__ mask){
  __shared__ float sc[LLEN];
  __shared__ unsigned long long wr[8];
  int b=blockIdx.x, tid=threadIdx.x, lane=tid&31, wid=tid>>5;
  uint32_t r1[2],r2[2],r3[2]; jax_subkeys(r1,r2,r3);
  for(int pass=0;pass<2;pass++){
    const uint32_t* key = pass?r2:r1;
    for(int l=tid;l<LLEN;l+=256){
      int j=b*LLEN+l;
      uint32_t i=(uint32_t)(j&8191), o0,o1;
      tf2x32(key[0],key[1],i,i+8192u,o0,o1);
      uint32_t bits=(j<8192)?o0:o1;
      float wv=mask[j]; if(pass) wv=1.0f-wv;
      sc[l]=__logf(wv+1e-20f)+gumbel_bits(bits);
    }
    __syncthreads();
    int* outI = pass?(g_idx2+b*32):(g_idx1+b*32);
    for(int j=0;j<32;j++){
      unsigned long long best=0ull;
      for(int l=tid;l<LLEN;l+=256){
        uint32_t fb=__float_as_uint(sc[l]);
        uint32_t u=(fb&0x80000000u)?(~fb):(fb|0x80000000u);
        unsigned long long k=((unsigned long long)u<<32)|(uint32_t)(LLEN-1-l);
        if(k>best) best=k;
      }
#pragma unroll
      for(int o=16;o;o>>=1){
        unsigned long long t=__shfl_xor_sync(0xffffffffu,best,o);
        if(t>best) best=t;
      }
      if(lane==0) wr[wid]=best;
      __syncthreads();
      if(tid==0){
        unsigned long long m=wr[0];
        for(int q=1;q<8;q++) if(wr[q]>m) m=wr[q];
        int l=LLEN-1-(int)(m&0xffffffffu);
        outI[j]=l; sc[l]=-INFINITY;
      }
      __syncthreads();
    }
  }
}

// ---------- fused: gather cols + fsa_sel small-GEMM + relation + selection + fpos ----------
// dynamic smem: fcols[256][36] | xcols[256][36] | fsel[256][36]  (110592 B)
__global__ void __launch_bounds__(256) k_select(const float* __restrict__ f,
                                                const float* __restrict__ ksa_w,
                                                const float* __restrict__ ksa_b){
  extern __shared__ float sm[];
  float* fcols=sm;
  float* xcols=sm+256*36;
  float* fsel =sm+2*256*36;
  __shared__ float rel[1024];
  __shared__ float nf[32],nx[32],f2[32];
  __shared__ int im[32],ik[32],selm[NN];
  int b=blockIdx.x, tid=threadIdx.x;
  if(tid<32){ im[tid]=g_idx1[b*32+tid]; ik[tid]=g_idx2[b*32+tid]; }
  __syncthreads();
  for(int i=tid;i<256*32;i+=256){
    int c=i>>5, j=i&31;
    fcols[c*36+j]=f   [((size_t)b*CC+c)*LLEN+im[j]];
    xcols[c*36+j]=g_xr[((size_t)b*CC+c)*LLEN+ik[j]];
  }
  __syncthreads();
  {
    int m=tid;
    float acc[32];
#pragma unroll
    for(int j=0;j<32;j++) acc[j]=0.f;
    const float* wrow=ksa_w+(size_t)m*CC;
    for(int c=0;c<CC;c++){
      float w=wrow[c];
      const float* fr=&fcols[c*36];
#pragma unroll
      for(int q=0;q<8;q++){
        float4 v=*(const float4*)(fr+q*4);
        acc[q*4+0]=fmaf(w,v.x,acc[q*4+0]);
        acc[q*4+1]=fmaf(w,v.y,acc[q*4+1]);
        acc[q*4+2]=fmaf(w,v.z,acc[q*4+2]);
        acc[q*4+3]=fmaf(w,v.w,acc[q*4+3]);
      }
    }
    float bv=ksa_b[m];
#pragma unroll
    for(int j=0;j<32;j++) fsel[m*36+j]=acc[j]+bv;
  }
  __syncthreads();
  if(tid<64){
    int j=tid&31;
    const float* base=(tid<32)?fsel:xcols;
    float s=0.f;
    for(int c=0;c<CC;c++){ float v=base[c*36+j]; s=fmaf(v,v,s); }
    if(tid<32) nf[j]=sqrtf(s); else nx[j]=sqrtf(s);
  }
  for(int p=tid;p<1024;p+=256){
    int m=p>>5, k=p&31;
    float s=0.f;
#pragma unroll 4
    for(int c=0;c<CC;c++) s=fmaf(fsel[c*36+m],xcols[c*36+k],s);
    rel[p]=s;
  }
  __syncthreads();
  if(tid<32){
    float mx=-INFINITY;
    for(int k=0;k<32;k++) mx=fmaxf(mx, rel[tid*32+k]/(nf[tid]*nx[k]+EPSF));
    f2[tid]=mx;
  }
  __syncthreads();
  if(tid==0){
    float mx=-INFINITY;
    for(int m=0;m<32;m++) mx=fmaxf(mx,f2[m]);
    float s=0.f;
    for(int m=0;m<32;m++){ f2[m]=__expf(f2[m]-mx); s+=f2[m]; }
    uint32_t r1k[2],r2k[2],r3k[2]; jax_subkeys(r1k,r2k,r3k);
    for(int m=0;m<32;m++){
      int j=b*32+m;
      uint32_t i=(uint32_t)(j&63),o0,o1;
      tf2x32(r3k[0],r3k[1],i,i+64u,o0,o1);
      uint32_t bits=(j<64)?o0:o1;
      f2[m]=__logf(f2[m]/s+1e-20f)+gumbel_bits(bits);
    }
    for(int j=0;j<NN;j++){
      float bv=-INFINITY; int bi=0;
      for(int m=0;m<32;m++) if(f2[m]>bv){bv=f2[m];bi=m;}
      selm[j]=bi; f2[bi]=-INFINITY;
    }
  }
  __syncthreads();
  {
    int c=tid;
#pragma unroll
    for(int j=0;j<NN;j++)
      g_fpos[((size_t)b*CC+c)*NN+j]=fsel[c*36+selm[j]];
  }
}

// ---------- fused act_pos + xn + softmax + cnt atomics ----------
__global__ void __launch_bounds__(128) k_att(const float* __restrict__ x,
                                             const float* __restrict__ kn,
                                             const float* __restrict__ alpha){
  __shared__ float fp_s[CC*NN];
  __shared__ float kn_s[CC*NN];
  __shared__ float al_s[NN];
  int b=blockIdx.y, tid=threadIdx.x, lane=tid&31;
  int l=blockIdx.x*128+tid;
  for(int i=tid;i<CC*NN;i+=128){
    fp_s[i]=g_fpos[(size_t)b*CC*NN+i];
    int c=i>>4, n=i&15;
    kn_s[i]=kn[n*CC+c];
  }
  if(tid<NN) al_s[tid]=fminf(fmaxf(alpha[tid],0.0f),1.0f);
  __syncthreads();
  float aa[NN],ax[NN];
#pragma unroll
  for(int n=0;n<NN;n++){aa[n]=0.f;ax[n]=0.f;}
  const float* xrp=g_xr+(size_t)b*CC*LLEN+l;
  const float* xp =x   +(size_t)b*CC*LLEN+l;
  for(int c=0;c<CC;c++){
    float xrv=__ldg(xrp+(size_t)c*LLEN);
    float xv =__ldg(xp +(size_t)c*LLEN);
    const float* fr=fp_s+c*NN;
    const float* kr=kn_s+c*NN;
#pragma unroll
    for(int n=0;n<NN;n++){
      aa[n]=fmaf(xrv,fr[n],aa[n]);
      ax[n]=fmaf(xv ,kr[n],ax[n]);
    }
  }
  float lg[NN],mx=-INFINITY;
#pragma unroll
  for(int n=0;n<NN;n++){ lg[n]=(al_s[n]*aa[n]+ax[n])*0.1f; mx=fmaxf(mx,lg[n]); }
  float s=0.f;
#pragma unroll
  for(int n=0;n<NN;n++){ lg[n]=__expf(lg[n]-mx); s+=lg[n]; }
  float inv=1.0f/s;
#pragma unroll
  for(int n=0;n<NN;n++){
    float v=lg[n]*inv;
    g_att[((size_t)b*NN+n)*LLEN+l]=v;
#pragma unroll
    for(int o=16;o;o>>=1) v+=__shfl_xor_sync(0xffffffffu,v,o);
    if(lane==0) atomicAdd(&g_cnt[b*NN+n], v);
  }
}

// ---------- per-(b,c,n) weighted moments -> P=1/(std+eps), Q=mean*P ----------
__global__ void __launch_bounds__(256) k_stats(){
  __shared__ float att_s[NN][258];
  __shared__ float xo_s[16][258];
  int b=blockIdx.y, c0=blockIdx.x*16, tid=threadIdx.x;
  int cr=tid>>4, n=tid&15;
  float s1=0.f,s2=0.f;
  for(int l0=0;l0<LLEN;l0+=256){
    for(int i=tid;i<16*256;i+=256){
      int r=i>>8, lc=i&255;
      att_s[r][lc]=g_att[((size_t)b*NN+r)*LLEN+l0+lc];
      xo_s [r][lc]=g_xo[((size_t)b*CC+c0+r)*LLEN+l0+lc];
    }
    __syncthreads();
#pragma unroll 4
    for(int lc=0;lc<256;lc+=2){
      float2 xv=*(float2*)&xo_s[cr][lc];
      float2 av=*(float2*)&att_s[n][lc];
      float h0=xv.x*av.x, h1=xv.y*av.y;
      s1+=h0+h1; s2=fmaf(h0,h0,fmaf(h1,h1,s2));
    }
    __syncthreads();
  }
  float cnt=g_cnt[b*NN+n]+EPSF;
  float mean=s1/cnt;
  float varsum=fmaf((float)LLEN*mean,mean, s2-2.0f*mean*s1);
  float stdv=sqrtf(fmaxf(varsum,0.0f)/cnt);
  float p=1.0f/(stdv+EPSF);
  size_t o=((size_t)b*CC+c0+cr)*NN+n;
  g_P[o]=p; g_Q[o]=mean*p;
}

// ---------- fused K=16 GEMMs + epilogue ----------
__global__ void __launch_bounds__(256) k_fuse(const float* __restrict__ x,
                                              const float* __restrict__ sigma,
                                              float* __restrict__ out){
  __shared__ float att_s[NN][64];
  __shared__ float P_s[16][16], Q_s[16][16];
  int b=blockIdx.z, c0=blockIdx.y*16, l0=blockIdx.x*64;
  int tid=threadIdx.x;
  for(int i=tid;i<NN*64;i+=256){
    int n=i>>6, l=i&63;
    att_s[n][l]=g_att[((size_t)b*NN+n)*LLEN+l0+l];
  }
  {
    int cl=tid>>4, n=tid&15;
    P_s[cl][n]=g_P[((size_t)b*CC+c0+cl)*NN+n];
    Q_s[cl][n]=g_Q[((size_t)b*CC+c0+cl)*NN+n];
  }
  __syncthreads();
  float sg=sigma[0];
  int ll=tid&63, cbase=tid>>6;
  for(int cc=cbase;cc<16;cc+=4){
    float r=0.f,s=0.f;
#pragma unroll
    for(int n=0;n<NN;n++){
      float a=att_s[n][ll];
      r=fmaf(P_s[cc][n],a,r);
      s=fmaf(Q_s[cc][n],a,s);
    }
    size_t o=((size_t)b*CC+c0+cc)*LLEN+l0+ll;
    out[o]=x[o]+sg*(g_xo[o]*r-s);
  }
}

extern "C" void kernel_launch(void* const* d_in, const int* in_sizes, int n_in,
                              void* d_out, int out_size){
  const float* x    =(const float*)d_in[0];
  const float* f    =(const float*)d_in[1];
  const float* mask =(const float*)d_in[2];
  const float* ksa_w=(const float*)d_in[3];
  const float* ksa_b=(const float*)d_in[4];
  const float* kr_w =(const float*)d_in[5];
  const float* kr_b =(const float*)d_in[6];
  const float* kn   =(const float*)d_in[7];
  const float* ko_w =(const float*)d_in[8];
  const float* ko_b =(const float*)d_in[9];
  const float* alpha=(const float*)d_in[10];
  const float* sigma=(const float*)d_in[11];
  float* out=(float*)d_out;

  float *xr,*xo,*cnt;
  cudaGetSymbolAddress((void**)&xr ,g_xr);
  cudaGetSymbolAddress((void**)&xo ,g_xo);
  cudaGetSymbolAddress((void**)&cnt,g_cnt);

  cudaFuncSetAttribute(k_gemm_dual, cudaFuncAttributeMaxDynamicSharedMemorySize, 50176);
  cudaFuncSetAttribute(k_select,    cudaFuncAttributeMaxDynamicSharedMemorySize, 110592);

  cudaMemsetAsync(cnt, 0, BB*NN*sizeof(float));
  k_sample<<<BB,256>>>(mask);
  dim3 gg(LLEN/GN, CC/GM, BB);
  k_gemm_dual<<<gg,256,50176>>>(kr_w,kr_b,ko_w,ko_b,x,xr,xo);
  k_select<<<BB,256,110592>>>(f,ksa_w,ksa_b);
  k_orth<<<1,256>>>(kn, out+(out_size-1));
  k_att<<<dim3(LLEN/128,BB),128>>>(x,kn,alpha);
  k_stats<<<dim3(CC/16,BB),256>>>();
  k_fuse<<<dim3(LLEN/64,CC/16,BB),256>>>(x,sigma,out);
}